// round 2
// baseline (speedup 1.0000x reference)
#include <cuda_runtime.h>
#include <cuda_bf16.h>
#include <math.h>

// Problem constants
#define BATCH 2
#define SEQ   1024
#define DM    1024
#define NH    64
#define NHK   8
#define HD    64
#define WIN   128
#define GQA   8          // NH / NHK
#define QKV_N 5120       // 4096 (Q) + 512 (K) + 512 (V)
#define K_OFF 4096
#define V_OFF 4608

// Scratch (device globals: no allocation allowed)
__device__ __align__(16) float g_qkv[BATCH * SEQ * QKV_N];   // [B*S, 5120]
__device__ __align__(16) float g_attn[BATCH * SEQ * NH * HD]; // [B*S, 4096]

// ---------------------------------------------------------------------------
// SGEMM:  C[M,N] = A[M,K] @ B[N,K]^T + bias[N]
// A row-major [M,K], B row-major [N,K] (weight layout as given).
// 128x128 tile, BK=8, 256 threads, 8x8 microtile. Requires M%128==0, N%128==0, K%8==0.
// ---------------------------------------------------------------------------
#define BM 128
#define BN 128
#define BK 8
#define TM 8
#define TN 8

__global__ __launch_bounds__(256) void sgemm_nt(
    const float* __restrict__ A, const float* __restrict__ B,
    const float* __restrict__ bias, float* __restrict__ C,
    int M, int N, int K, int ldc)
{
    __shared__ float As[BK][BM];
    __shared__ float Bs[BK][BN];

    const int bx = blockIdx.x;   // N tile
    const int by = blockIdx.y;   // M tile
    const int tid = threadIdx.x;
    const int tx = tid & 15;     // 0..15 -> column group
    const int ty = tid >> 4;     // 0..15 -> row group

    const float* Aptr = A + (size_t)(by * BM) * K;
    const float* Bptr = B + (size_t)(bx * BN) * K;

    const int lrow = tid >> 1;          // 0..127
    const int lcol = (tid & 1) * 4;     // 0 or 4

    float acc[TM][TN];
#pragma unroll
    for (int i = 0; i < TM; i++)
#pragma unroll
        for (int j = 0; j < TN; j++) acc[i][j] = 0.0f;

    for (int k0 = 0; k0 < K; k0 += BK) {
        float4 av = *(const float4*)(Aptr + (size_t)lrow * K + k0 + lcol);
        float4 bv = *(const float4*)(Bptr + (size_t)lrow * K + k0 + lcol);
        As[lcol + 0][lrow] = av.x;
        As[lcol + 1][lrow] = av.y;
        As[lcol + 2][lrow] = av.z;
        As[lcol + 3][lrow] = av.w;
        Bs[lcol + 0][lrow] = bv.x;
        Bs[lcol + 1][lrow] = bv.y;
        Bs[lcol + 2][lrow] = bv.z;
        Bs[lcol + 3][lrow] = bv.w;
        __syncthreads();

#pragma unroll
        for (int k = 0; k < BK; k++) {
            float a[TM], b[TN];
            *(float4*)&a[0] = *(const float4*)&As[k][ty * TM];
            *(float4*)&a[4] = *(const float4*)&As[k][ty * TM + 4];
            *(float4*)&b[0] = *(const float4*)&Bs[k][tx * TN];
            *(float4*)&b[4] = *(const float4*)&Bs[k][tx * TN + 4];
#pragma unroll
            for (int i = 0; i < TM; i++)
#pragma unroll
                for (int j = 0; j < TN; j++)
                    acc[i][j] = fmaf(a[i], b[j], acc[i][j]);
        }
        __syncthreads();
    }

    // Epilogue with bias
#pragma unroll
    for (int i = 0; i < TM; i++) {
        int row = by * BM + ty * TM + i;
        float* crow = C + (size_t)row * ldc + bx * BN + tx * TN;
        const float* brow = bias + bx * BN + tx * TN;
#pragma unroll
        for (int j = 0; j < TN; j += 4) {
            float4 o;
            o.x = acc[i][j + 0] + brow[j + 0];
            o.y = acc[i][j + 1] + brow[j + 1];
            o.z = acc[i][j + 2] + brow[j + 2];
            o.w = acc[i][j + 3] + brow[j + 3];
            *(float4*)(crow + j) = o;
        }
    }
}

// ---------------------------------------------------------------------------
// Sliding-window GQA attention with sink logit.
// One CTA per (query position, kv-head, batch); 8 query heads share K/V.
// 128 threads.
// ---------------------------------------------------------------------------
__global__ __launch_bounds__(128) void attn_kernel(
    const float* __restrict__ qkv,   // [B*S, 5120]
    const float* __restrict__ sinks, // [64]
    float* __restrict__ out)         // [B*S, 4096]
{
    const int q  = blockIdx.x;
    const int hk = blockIdx.y;
    const int b  = blockIdx.z;
    const int kstart = (q >= WIN - 1) ? (q - WIN + 1) : 0;
    const int nk = q - kstart + 1;   // <= 128
    const int tid = threadIdx.x;

    __shared__ float  q_s[GQA * HD];     // 512 floats
    __shared__ float4 v_s[WIN * 16];     // 128 keys x 64 dims
    __shared__ float  sc_s[GQA][WIN];
    __shared__ float  inv_s[GQA];

    // Load Q for the 8 grouped heads (contiguous 512 floats)
    {
        const float4* qrow = (const float4*)(qkv + ((size_t)(b * SEQ + q)) * QKV_N + hk * (GQA * HD));
        ((float4*)q_s)[tid] = qrow[tid];   // 128 float4 = 512 floats
    }
    // Load V window into smem
    for (int idx = tid; idx < nk * 16; idx += 128) {
        int j = idx >> 4, d4 = idx & 15;
        v_s[(j << 4) + d4] = *(const float4*)(
            qkv + ((size_t)(b * SEQ + kstart + j)) * QKV_N + V_OFF + hk * HD + d4 * 4);
    }
    __syncthreads();

    // Scores: thread j handles key j, computes dot with all 8 heads' q
    if (tid < nk) {
        const float4* krow = (const float4*)(
            qkv + ((size_t)(b * SEQ + kstart + tid)) * QKV_N + K_OFF + hk * HD);
        float4 kf[16];
#pragma unroll
        for (int i = 0; i < 16; i++) kf[i] = krow[i];
#pragma unroll
        for (int h = 0; h < GQA; h++) {
            const float4* qh = ((const float4*)q_s) + h * 16;
            float s = 0.0f;
#pragma unroll
            for (int i = 0; i < 16; i++) {
                float4 qv = qh[i];
                s = fmaf(kf[i].x, qv.x, s);
                s = fmaf(kf[i].y, qv.y, s);
                s = fmaf(kf[i].z, qv.z, s);
                s = fmaf(kf[i].w, qv.w, s);
            }
            sc_s[h][tid] = s * 0.125f;   // 1/sqrt(64)
        }
    }
    __syncthreads();

    // Softmax with sink column: warp w handles heads 2w and 2w+1
    {
        const int wid = tid >> 5, lane = tid & 31;
#pragma unroll
        for (int hh = 0; hh < 2; hh++) {
            int h = wid * 2 + hh;
            float sink = sinks[hk * GQA + h];
            float m = sink;
            for (int j = lane; j < nk; j += 32) m = fmaxf(m, sc_s[h][j]);
#pragma unroll
            for (int o = 16; o > 0; o >>= 1) m = fmaxf(m, __shfl_xor_sync(0xFFFFFFFFu, m, o));
            float sum = 0.0f;
            for (int j = lane; j < nk; j += 32) {
                float e = __expf(sc_s[h][j] - m);
                sc_s[h][j] = e;
                sum += e;
            }
#pragma unroll
            for (int o = 16; o > 0; o >>= 1) sum += __shfl_xor_sync(0xFFFFFFFFu, sum, o);
            sum += __expf(sink - m);
            if (lane == 0) inv_s[h] = 1.0f / sum;
        }
    }
    __syncthreads();

    // PV: thread t -> head t>>4, dims (t&15)*4 .. +3
    {
        const int h = tid >> 4, d4 = tid & 15;
        float4 acc = make_float4(0.f, 0.f, 0.f, 0.f);
        for (int j = 0; j < nk; j++) {
            float p = sc_s[h][j];
            float4 v = v_s[(j << 4) + d4];
            acc.x = fmaf(p, v.x, acc.x);
            acc.y = fmaf(p, v.y, acc.y);
            acc.z = fmaf(p, v.z, acc.z);
            acc.w = fmaf(p, v.w, acc.w);
        }
        float inv = inv_s[h];
        acc.x *= inv; acc.y *= inv; acc.z *= inv; acc.w *= inv;
        *(float4*)(out + ((size_t)(b * SEQ + q)) * (NH * HD) + (hk * GQA + h) * HD + d4 * 4) = acc;
    }
}

// ---------------------------------------------------------------------------
// kernel_launch
// Inputs: x, Wq, bq, Wk, bk, Wv, bv, Wo, bo, sinks
// ---------------------------------------------------------------------------
extern "C" void kernel_launch(void* const* d_in, const int* in_sizes, int n_in,
                              void* d_out, int out_size)
{
    const float* x    = (const float*)d_in[0];
    const float* Wq   = (const float*)d_in[1];
    const float* bq   = (const float*)d_in[2];
    const float* Wk   = (const float*)d_in[3];
    const float* bk   = (const float*)d_in[4];
    const float* Wv   = (const float*)d_in[5];
    const float* bv   = (const float*)d_in[6];
    const float* Wo   = (const float*)d_in[7];
    const float* bo   = (const float*)d_in[8];
    const float* sinks = (const float*)d_in[9];
    float* out = (float*)d_out;

    float* qkv = nullptr;
    float* attn = nullptr;
    cudaGetSymbolAddress((void**)&qkv, g_qkv);
    cudaGetSymbolAddress((void**)&attn, g_attn);

    const int M = BATCH * SEQ;   // 2048

    // QKV projections into segmented buffer [M, 5120]
    {
        dim3 grid(NH * HD / BN, M / BM);       // 32 x 16
        sgemm_nt<<<grid, 256>>>(x, Wq, bq, qkv + 0, M, NH * HD, DM, QKV_N);
    }
    {
        dim3 grid(NHK * HD / BN, M / BM);      // 4 x 16
        sgemm_nt<<<grid, 256>>>(x, Wk, bk, qkv + K_OFF, M, NHK * HD, DM, QKV_N);
        sgemm_nt<<<grid, 256>>>(x, Wv, bv, qkv + V_OFF, M, NHK * HD, DM, QKV_N);
    }

    // Attention
    {
        dim3 grid(SEQ, NHK, BATCH);            // 1024 x 8 x 2
        attn_kernel<<<grid, 128>>>(qkv, sinks, attn);
    }

    // Output projection: C[M, DM] = attn[M, NH*HD] @ Wo[DM, NH*HD]^T + bo
    {
        dim3 grid(DM / BN, M / BM);            // 8 x 16
        sgemm_nt<<<grid, 256>>>(attn, Wo, bo, out, M, DM, NH * HD, DM);
    }
}

// round 3
// speedup vs baseline: 2.5930x; 2.5930x over previous
#include <cuda_runtime.h>
#include <cuda_bf16.h>
#include <math.h>

// Problem constants
#define BATCH 2
#define SEQ   1024
#define DM    1024
#define NH    64
#define NHK   8
#define HD    64
#define WIN   128
#define GQA   8          // NH / NHK
#define QKV_N 5120       // 4096 (Q) + 512 (K) + 512 (V)
#define K_OFF 4096
#define V_OFF 4608

// Scratch (device globals: no allocation allowed)
__device__ __align__(16) float g_qkv[BATCH * SEQ * QKV_N];    // [B*S, 5120]
__device__ __align__(16) float g_attn[BATCH * SEQ * NH * HD]; // [B*S, 4096]

// ---------------------------------------------------------------------------
// TF32 tensor-core GEMM:  C[M,N] = A[M,K] @ B[N,K]^T + bias[N]
// A row-major [M,K], B row-major [N,K]. CTA tile 128x128, BK=32.
// 256 threads = 8 warps, each warp computes a 32(M) x 64(N) tile via
// mma.sync.m16n8k8 tf32 (2 M-tiles x 8 N-tiles per k-step).
// Requires M%128==0, N%128==0, K%32==0.
// ---------------------------------------------------------------------------
#define GPAD 36   // padded smem row (words): bank = (4*g + t) -> conflict-free

__device__ __forceinline__ unsigned f2tf32(float x) {
    unsigned u;
    asm("cvt.rna.tf32.f32 %0, %1;" : "=r"(u) : "f"(x));
    return u;
}

__device__ __forceinline__ void mma_tf32(float* c, const unsigned* a, const unsigned* b) {
    asm volatile(
        "mma.sync.aligned.m16n8k8.row.col.f32.tf32.tf32.f32 "
        "{%0,%1,%2,%3}, {%4,%5,%6,%7}, {%8,%9}, {%0,%1,%2,%3};"
        : "+f"(c[0]), "+f"(c[1]), "+f"(c[2]), "+f"(c[3])
        : "r"(a[0]), "r"(a[1]), "r"(a[2]), "r"(a[3]), "r"(b[0]), "r"(b[1]));
}

__global__ __launch_bounds__(256) void tf32_gemm_nt(
    const float* __restrict__ A, const float* __restrict__ B,
    const float* __restrict__ bias, float* __restrict__ C,
    int M, int N, int K, int ldc)
{
    __shared__ unsigned As[128][GPAD];
    __shared__ unsigned Bs[128][GPAD];

    const int tid  = threadIdx.x;
    const int wid  = tid >> 5;
    const int lane = tid & 31;
    const int wm   = wid & 3;     // M warp index (0..3) -> rows wm*32
    const int wn   = wid >> 2;    // N warp index (0..1) -> cols wn*64
    const int g    = lane >> 2;   // group id 0..7
    const int t    = lane & 3;    // thread-in-group 0..3

    const float* Ag = A + (size_t)(blockIdx.y * 128) * K;
    const float* Bg = B + (size_t)(blockIdx.x * 128) * K;

    float acc[2][8][4];
#pragma unroll
    for (int mt = 0; mt < 2; mt++)
#pragma unroll
        for (int nt = 0; nt < 8; nt++)
#pragma unroll
            for (int i = 0; i < 4; i++) acc[mt][nt][i] = 0.0f;

    // register staging for global tiles (4 float4 each for A and B)
    float4 stA[4], stB[4];

    const int niter = K >> 5;

    // prologue load (tile 0)
#pragma unroll
    for (int p = 0; p < 4; p++) {
        int f = tid + p * 256;
        int row = f >> 3, c4 = f & 7;
        stA[p] = *(const float4*)(Ag + (size_t)row * K + c4 * 4);
        stB[p] = *(const float4*)(Bg + (size_t)row * K + c4 * 4);
    }

    for (int it = 0; it < niter; it++) {
        __syncthreads();   // previous compute done reading smem
        // convert + store staged tile to smem
#pragma unroll
        for (int p = 0; p < 4; p++) {
            int f = tid + p * 256;
            int row = f >> 3, c4 = f & 7;
            unsigned* pa = &As[row][c4 * 4];
            pa[0] = f2tf32(stA[p].x); pa[1] = f2tf32(stA[p].y);
            pa[2] = f2tf32(stA[p].z); pa[3] = f2tf32(stA[p].w);
            unsigned* pb = &Bs[row][c4 * 4];
            pb[0] = f2tf32(stB[p].x); pb[1] = f2tf32(stB[p].y);
            pb[2] = f2tf32(stB[p].z); pb[3] = f2tf32(stB[p].w);
        }
        __syncthreads();

        // prefetch next tile (overlaps with MMA compute below)
        if (it + 1 < niter) {
            int k0 = (it + 1) << 5;
#pragma unroll
            for (int p = 0; p < 4; p++) {
                int f = tid + p * 256;
                int row = f >> 3, c4 = f & 7;
                stA[p] = *(const float4*)(Ag + (size_t)row * K + k0 + c4 * 4);
                stB[p] = *(const float4*)(Bg + (size_t)row * K + k0 + c4 * 4);
            }
        }

        // compute: 4 k-steps of k=8
#pragma unroll
        for (int kk = 0; kk < 4; kk++) {
            const int k = kk * 8;
            unsigned a[2][4], b[8][2];
#pragma unroll
            for (int mt = 0; mt < 2; mt++) {
                const int rb = wm * 32 + mt * 16;
                a[mt][0] = As[rb + g][k + t];
                a[mt][1] = As[rb + 8 + g][k + t];
                a[mt][2] = As[rb + g][k + 4 + t];
                a[mt][3] = As[rb + 8 + g][k + 4 + t];
            }
#pragma unroll
            for (int nt = 0; nt < 8; nt++) {
                const int nb = wn * 64 + nt * 8;
                b[nt][0] = Bs[nb + g][k + t];
                b[nt][1] = Bs[nb + g][k + 4 + t];
            }
#pragma unroll
            for (int mt = 0; mt < 2; mt++)
#pragma unroll
                for (int nt = 0; nt < 8; nt++)
                    mma_tf32(acc[mt][nt], a[mt], b[nt]);
        }
    }

    // epilogue with bias (float2 stores)
#pragma unroll
    for (int mt = 0; mt < 2; mt++) {
        const int row0 = blockIdx.y * 128 + wm * 32 + mt * 16 + g;
#pragma unroll
        for (int nt = 0; nt < 8; nt++) {
            const int col = blockIdx.x * 128 + wn * 64 + nt * 8 + 2 * t;
            const float b0 = bias[col], b1 = bias[col + 1];
            float2 o0 = make_float2(acc[mt][nt][0] + b0, acc[mt][nt][1] + b1);
            float2 o1 = make_float2(acc[mt][nt][2] + b0, acc[mt][nt][3] + b1);
            *(float2*)(C + (size_t)row0 * ldc + col) = o0;
            *(float2*)(C + (size_t)(row0 + 8) * ldc + col) = o1;
        }
    }
}

// ---------------------------------------------------------------------------
// Sliding-window GQA attention with sink logit.
// One CTA per (query position, kv-head, batch); 8 query heads share K/V.
// 128 threads. (unchanged from R2 baseline)
// ---------------------------------------------------------------------------
__global__ __launch_bounds__(128) void attn_kernel(
    const float* __restrict__ qkv,   // [B*S, 5120]
    const float* __restrict__ sinks, // [64]
    float* __restrict__ out)         // [B*S, 4096]
{
    const int q  = blockIdx.x;
    const int hk = blockIdx.y;
    const int b  = blockIdx.z;
    const int kstart = (q >= WIN - 1) ? (q - WIN + 1) : 0;
    const int nk = q - kstart + 1;   // <= 128
    const int tid = threadIdx.x;

    __shared__ float  q_s[GQA * HD];     // 512 floats
    __shared__ float4 v_s[WIN * 16];     // 128 keys x 64 dims
    __shared__ float  sc_s[GQA][WIN];
    __shared__ float  inv_s[GQA];

    {
        const float4* qrow = (const float4*)(qkv + ((size_t)(b * SEQ + q)) * QKV_N + hk * (GQA * HD));
        ((float4*)q_s)[tid] = qrow[tid];
    }
    for (int idx = tid; idx < nk * 16; idx += 128) {
        int j = idx >> 4, d4 = idx & 15;
        v_s[(j << 4) + d4] = *(const float4*)(
            qkv + ((size_t)(b * SEQ + kstart + j)) * QKV_N + V_OFF + hk * HD + d4 * 4);
    }
    __syncthreads();

    if (tid < nk) {
        const float4* krow = (const float4*)(
            qkv + ((size_t)(b * SEQ + kstart + tid)) * QKV_N + K_OFF + hk * HD);
        float4 kf[16];
#pragma unroll
        for (int i = 0; i < 16; i++) kf[i] = krow[i];
#pragma unroll
        for (int h = 0; h < GQA; h++) {
            const float4* qh = ((const float4*)q_s) + h * 16;
            float s = 0.0f;
#pragma unroll
            for (int i = 0; i < 16; i++) {
                float4 qv = qh[i];
                s = fmaf(kf[i].x, qv.x, s);
                s = fmaf(kf[i].y, qv.y, s);
                s = fmaf(kf[i].z, qv.z, s);
                s = fmaf(kf[i].w, qv.w, s);
            }
            sc_s[h][tid] = s * 0.125f;   // 1/sqrt(64)
        }
    }
    __syncthreads();

    {
        const int wid = tid >> 5, lane = tid & 31;
#pragma unroll
        for (int hh = 0; hh < 2; hh++) {
            int h = wid * 2 + hh;
            float sink = sinks[hk * GQA + h];
            float m = sink;
            for (int j = lane; j < nk; j += 32) m = fmaxf(m, sc_s[h][j]);
#pragma unroll
            for (int o = 16; o > 0; o >>= 1) m = fmaxf(m, __shfl_xor_sync(0xFFFFFFFFu, m, o));
            float sum = 0.0f;
            for (int j = lane; j < nk; j += 32) {
                float e = __expf(sc_s[h][j] - m);
                sc_s[h][j] = e;
                sum += e;
            }
#pragma unroll
            for (int o = 16; o > 0; o >>= 1) sum += __shfl_xor_sync(0xFFFFFFFFu, sum, o);
            sum += __expf(sink - m);
            if (lane == 0) inv_s[h] = 1.0f / sum;
        }
    }
    __syncthreads();

    {
        const int h = tid >> 4, d4 = tid & 15;
        float4 acc = make_float4(0.f, 0.f, 0.f, 0.f);
        for (int j = 0; j < nk; j++) {
            float p = sc_s[h][j];
            float4 v = v_s[(j << 4) + d4];
            acc.x = fmaf(p, v.x, acc.x);
            acc.y = fmaf(p, v.y, acc.y);
            acc.z = fmaf(p, v.z, acc.z);
            acc.w = fmaf(p, v.w, acc.w);
        }
        float inv = inv_s[h];
        acc.x *= inv; acc.y *= inv; acc.z *= inv; acc.w *= inv;
        *(float4*)(out + ((size_t)(b * SEQ + q)) * (NH * HD) + (hk * GQA + h) * HD + d4 * 4) = acc;
    }
}

// ---------------------------------------------------------------------------
// kernel_launch
// Inputs: x, Wq, bq, Wk, bk, Wv, bv, Wo, bo, sinks
// ---------------------------------------------------------------------------
extern "C" void kernel_launch(void* const* d_in, const int* in_sizes, int n_in,
                              void* d_out, int out_size)
{
    const float* x    = (const float*)d_in[0];
    const float* Wq   = (const float*)d_in[1];
    const float* bq   = (const float*)d_in[2];
    const float* Wk   = (const float*)d_in[3];
    const float* bk   = (const float*)d_in[4];
    const float* Wv   = (const float*)d_in[5];
    const float* bv   = (const float*)d_in[6];
    const float* Wo   = (const float*)d_in[7];
    const float* bo   = (const float*)d_in[8];
    const float* sinks = (const float*)d_in[9];
    float* out = (float*)d_out;

    float* qkv = nullptr;
    float* attn = nullptr;
    cudaGetSymbolAddress((void**)&qkv, g_qkv);
    cudaGetSymbolAddress((void**)&attn, g_attn);

    const int M = BATCH * SEQ;   // 2048

    // QKV projections into segmented buffer [M, 5120]
    {
        dim3 grid(NH * HD / 128, M / 128);     // 32 x 16
        tf32_gemm_nt<<<grid, 256>>>(x, Wq, bq, qkv + 0, M, NH * HD, DM, QKV_N);
    }
    {
        dim3 grid(NHK * HD / 128, M / 128);    // 4 x 16
        tf32_gemm_nt<<<grid, 256>>>(x, Wk, bk, qkv + K_OFF, M, NHK * HD, DM, QKV_N);
        tf32_gemm_nt<<<grid, 256>>>(x, Wv, bv, qkv + V_OFF, M, NHK * HD, DM, QKV_N);
    }

    // Attention
    {
        dim3 grid(SEQ, NHK, BATCH);            // 1024 x 8 x 2
        attn_kernel<<<grid, 128>>>(qkv, sinks, attn);
    }

    // Output projection: C[M, DM] = attn[M, NH*HD] @ Wo[DM, NH*HD]^T + bo
    {
        dim3 grid(DM / 128, M / 128);          // 8 x 16
        tf32_gemm_nt<<<grid, 256>>>(attn, Wo, bo, out, M, DM, NH * HD, DM);
    }
}

// round 4
// speedup vs baseline: 4.1405x; 1.5968x over previous
#include <cuda_runtime.h>
#include <cuda_bf16.h>
#include <math.h>

// Problem constants
#define BATCH 2
#define SEQ   1024
#define DM    1024
#define NH    64
#define NHK   8
#define HD    64
#define WIN   128
#define GQA   8          // NH / NHK
#define QKV_N 5120       // 4096 (Q) + 512 (K) + 512 (V)
#define K_OFF 4096
#define V_OFF 4608

// Scratch (device globals: no allocation allowed)
__device__ __align__(16) float g_qkv[BATCH * SEQ * QKV_N];    // [B*S, 5120]
__device__ __align__(16) float g_attn[BATCH * SEQ * NH * HD]; // [B*S, 4096]

// ---------------------------------------------------------------------------
// TF32 helpers
// ---------------------------------------------------------------------------
__device__ __forceinline__ unsigned f2tf32(float x) {
    unsigned u;
    asm("cvt.rna.tf32.f32 %0, %1;" : "=r"(u) : "f"(x));
    return u;
}

__device__ __forceinline__ void mma_tf32(float* c, const unsigned* a, const unsigned* b) {
    asm volatile(
        "mma.sync.aligned.m16n8k8.row.col.f32.tf32.tf32.f32 "
        "{%0,%1,%2,%3}, {%4,%5,%6,%7}, {%8,%9}, {%0,%1,%2,%3};"
        : "+f"(c[0]), "+f"(c[1]), "+f"(c[2]), "+f"(c[3])
        : "r"(a[0]), "r"(a[1]), "r"(a[2]), "r"(a[3]), "r"(b[0]), "r"(b[1]));
}

// ---------------------------------------------------------------------------
// TF32 tensor-core GEMM:  C[M,N] = A[M,K] @ B[N,K]^T + bias[N]   (from R3)
// ---------------------------------------------------------------------------
#define GPAD 36

__global__ __launch_bounds__(256) void tf32_gemm_nt(
    const float* __restrict__ A, const float* __restrict__ B,
    const float* __restrict__ bias, float* __restrict__ C,
    int M, int N, int K, int ldc)
{
    __shared__ unsigned As[128][GPAD];
    __shared__ unsigned Bs[128][GPAD];

    const int tid  = threadIdx.x;
    const int wid  = tid >> 5;
    const int lane = tid & 31;
    const int wm   = wid & 3;
    const int wn   = wid >> 2;
    const int g    = lane >> 2;
    const int t    = lane & 3;

    const float* Ag = A + (size_t)(blockIdx.y * 128) * K;
    const float* Bg = B + (size_t)(blockIdx.x * 128) * K;

    float acc[2][8][4];
#pragma unroll
    for (int mt = 0; mt < 2; mt++)
#pragma unroll
        for (int nt = 0; nt < 8; nt++)
#pragma unroll
            for (int i = 0; i < 4; i++) acc[mt][nt][i] = 0.0f;

    float4 stA[4], stB[4];
    const int niter = K >> 5;

#pragma unroll
    for (int p = 0; p < 4; p++) {
        int f = tid + p * 256;
        int row = f >> 3, c4 = f & 7;
        stA[p] = *(const float4*)(Ag + (size_t)row * K + c4 * 4);
        stB[p] = *(const float4*)(Bg + (size_t)row * K + c4 * 4);
    }

    for (int it = 0; it < niter; it++) {
        __syncthreads();
#pragma unroll
        for (int p = 0; p < 4; p++) {
            int f = tid + p * 256;
            int row = f >> 3, c4 = f & 7;
            unsigned* pa = &As[row][c4 * 4];
            pa[0] = f2tf32(stA[p].x); pa[1] = f2tf32(stA[p].y);
            pa[2] = f2tf32(stA[p].z); pa[3] = f2tf32(stA[p].w);
            unsigned* pb = &Bs[row][c4 * 4];
            pb[0] = f2tf32(stB[p].x); pb[1] = f2tf32(stB[p].y);
            pb[2] = f2tf32(stB[p].z); pb[3] = f2tf32(stB[p].w);
        }
        __syncthreads();

        if (it + 1 < niter) {
            int k0 = (it + 1) << 5;
#pragma unroll
            for (int p = 0; p < 4; p++) {
                int f = tid + p * 256;
                int row = f >> 3, c4 = f & 7;
                stA[p] = *(const float4*)(Ag + (size_t)row * K + k0 + c4 * 4);
                stB[p] = *(const float4*)(Bg + (size_t)row * K + k0 + c4 * 4);
            }
        }

#pragma unroll
        for (int kk = 0; kk < 4; kk++) {
            const int k = kk * 8;
            unsigned a[2][4], b[8][2];
#pragma unroll
            for (int mt = 0; mt < 2; mt++) {
                const int rb = wm * 32 + mt * 16;
                a[mt][0] = As[rb + g][k + t];
                a[mt][1] = As[rb + 8 + g][k + t];
                a[mt][2] = As[rb + g][k + 4 + t];
                a[mt][3] = As[rb + 8 + g][k + 4 + t];
            }
#pragma unroll
            for (int nt = 0; nt < 8; nt++) {
                const int nb = wn * 64 + nt * 8;
                b[nt][0] = Bs[nb + g][k + t];
                b[nt][1] = Bs[nb + g][k + 4 + t];
            }
#pragma unroll
            for (int mt = 0; mt < 2; mt++)
#pragma unroll
                for (int nt = 0; nt < 8; nt++)
                    mma_tf32(acc[mt][nt], a[mt], b[nt]);
        }
    }

#pragma unroll
    for (int mt = 0; mt < 2; mt++) {
        const int row0 = blockIdx.y * 128 + wm * 32 + mt * 16 + g;
#pragma unroll
        for (int nt = 0; nt < 8; nt++) {
            const int col = blockIdx.x * 128 + wn * 64 + nt * 8 + 2 * t;
            const float b0 = bias[col], b1 = bias[col + 1];
            float2 o0 = make_float2(acc[mt][nt][0] + b0, acc[mt][nt][1] + b1);
            float2 o1 = make_float2(acc[mt][nt][2] + b0, acc[mt][nt][3] + b1);
            *(float2*)(C + (size_t)row0 * ldc + col) = o0;
            *(float2*)(C + (size_t)(row0 + 8) * ldc + col) = o1;
        }
    }
}

// ---------------------------------------------------------------------------
// Flash-style sliding-window GQA attention with sink logit (tensor cores).
// CTA = (32-query tile, kv-head, batch). 256 threads = 8 warps.
// Warp w = head w: rows = 32 queries for that head (2 m16 tiles).
// Q in registers (tf32 A-fragments). Loop over <=5 key chunks of 32:
//   K chunk -> smem -> QK^T MMA -> online softmax -> P via smem -> PV MMA.
// ---------------------------------------------------------------------------
#define KC   32          // keys per chunk
#define KPAD 68          // K/V smem row stride (words): 64 + 4
#define PPAD 36          // P smem row stride (words): 32 + 4
#define KS_OFF 0                          // Ks: [32][68]
#define VS_OFF (KC * KPAD)                // Vs: [32][68]
#define PS_OFF (2 * KC * KPAD)            // Ps: [256][36]
#define ATTN_SMEM ((2 * KC * KPAD + 256 * PPAD) * 4)  // 54272 bytes

__global__ __launch_bounds__(256) void attn_mma_kernel(
    const float* __restrict__ qkv,   // [B*S, 5120]
    const float* __restrict__ sinks, // [64]
    float* __restrict__ out)         // [B*S, 4096]
{
    extern __shared__ unsigned smem[];
    unsigned* Ks = smem + KS_OFF;
    unsigned* Vs = smem + VS_OFF;
    unsigned* Ps = smem + PS_OFF;

    const int q0  = blockIdx.x * 32;
    const int hk  = blockIdx.y;
    const int b   = blockIdx.z;
    const int tid = threadIdx.x;
    const int wid = tid >> 5;       // warp = head (0..7)
    const int lane = tid & 31;
    const int g = lane >> 2;
    const int t = lane & 3;

    const int kbase = (q0 >= 128) ? (q0 - 128) : 0;
    const int nch = (q0 + 32 - kbase) >> 5;     // 1..5 chunks

    // --- Load Q fragments (2 m16 tiles x 8 k-steps) straight from global ---
    unsigned qa[2][8][4];
    {
        const float* qrow = qkv + ((size_t)(b * SEQ + q0)) * QKV_N + hk * 512 + wid * 64;
#pragma unroll
        for (int mt = 0; mt < 2; mt++) {
            const float* r0 = qrow + (size_t)(mt * 16 + g) * QKV_N;
            const float* r1 = r0 + (size_t)8 * QKV_N;
#pragma unroll
            for (int k = 0; k < 8; k++) {
                qa[mt][k][0] = f2tf32(r0[8 * k + t]);
                qa[mt][k][1] = f2tf32(r1[8 * k + t]);
                qa[mt][k][2] = f2tf32(r0[8 * k + t + 4]);
                qa[mt][k][3] = f2tf32(r1[8 * k + t + 4]);
            }
        }
    }

    const float sink = sinks[hk * GQA + wid];
    float m[2][2], l[2][2];
#pragma unroll
    for (int mt = 0; mt < 2; mt++) { m[mt][0] = sink; m[mt][1] = sink; l[mt][0] = 0.f; l[mt][1] = 0.f; }

    float o[2][8][4];
#pragma unroll
    for (int mt = 0; mt < 2; mt++)
#pragma unroll
        for (int nt = 0; nt < 8; nt++)
#pragma unroll
            for (int i = 0; i < 4; i++) o[mt][nt][i] = 0.0f;

    const int ldrow = tid >> 4;      // 0..15 (key within chunk, x2 below)
    const int ldc4  = tid & 15;      // float4 within 64 dims

    for (int ch = 0; ch < nch; ch++) {
        const int kb = kbase + ch * KC;
        __syncthreads();   // previous chunk's PV reads done
        // Load K/V chunk (32 keys x 64 dims each), convert to tf32
        {
            const size_t rowbase = ((size_t)(b * SEQ + kb + ldrow)) * QKV_N + hk * 64;
            const size_t rowbase2 = rowbase + (size_t)16 * QKV_N;
            float4 kv0 = *(const float4*)(qkv + rowbase + K_OFF - hk * 64 + hk * 64 + ldc4 * 4);
            float4 kv1 = *(const float4*)(qkv + rowbase2 + K_OFF - hk * 64 + hk * 64 + ldc4 * 4);
            float4 vv0 = *(const float4*)(qkv + rowbase + V_OFF - hk * 64 + hk * 64 + ldc4 * 4);
            float4 vv1 = *(const float4*)(qkv + rowbase2 + V_OFF - hk * 64 + hk * 64 + ldc4 * 4);
            unsigned* pk0 = &Ks[ldrow * KPAD + ldc4 * 4];
            unsigned* pk1 = &Ks[(ldrow + 16) * KPAD + ldc4 * 4];
            unsigned* pv0 = &Vs[ldrow * KPAD + ldc4 * 4];
            unsigned* pv1 = &Vs[(ldrow + 16) * KPAD + ldc4 * 4];
            pk0[0] = f2tf32(kv0.x); pk0[1] = f2tf32(kv0.y); pk0[2] = f2tf32(kv0.z); pk0[3] = f2tf32(kv0.w);
            pk1[0] = f2tf32(kv1.x); pk1[1] = f2tf32(kv1.y); pk1[2] = f2tf32(kv1.z); pk1[3] = f2tf32(kv1.w);
            pv0[0] = f2tf32(vv0.x); pv0[1] = f2tf32(vv0.y); pv0[2] = f2tf32(vv0.z); pv0[3] = f2tf32(vv0.w);
            pv1[0] = f2tf32(vv1.x); pv1[1] = f2tf32(vv1.y); pv1[2] = f2tf32(vv1.z); pv1[3] = f2tf32(vv1.w);
        }
        __syncthreads();

        // ---- QK^T: scores [32 rows][32 keys] per warp ----
        float sc[2][4][4];
#pragma unroll
        for (int mt = 0; mt < 2; mt++)
#pragma unroll
            for (int nt = 0; nt < 4; nt++)
#pragma unroll
                for (int i = 0; i < 4; i++) sc[mt][nt][i] = 0.0f;

#pragma unroll
        for (int k = 0; k < 8; k++) {
            unsigned bfr[4][2];
#pragma unroll
            for (int nt = 0; nt < 4; nt++) {
                bfr[nt][0] = Ks[(nt * 8 + g) * KPAD + 8 * k + t];
                bfr[nt][1] = Ks[(nt * 8 + g) * KPAD + 8 * k + t + 4];
            }
#pragma unroll
            for (int mt = 0; mt < 2; mt++)
#pragma unroll
                for (int nt = 0; nt < 4; nt++)
                    mma_tf32(sc[mt][nt], qa[mt][k], bfr[nt]);
        }

        // ---- mask + online softmax + write P ----
#pragma unroll
        for (int mt = 0; mt < 2; mt++) {
            const int qr0 = q0 + mt * 16 + g;
            const int qr1 = qr0 + 8;
            float mx0 = -1e30f, mx1 = -1e30f;
#pragma unroll
            for (int nt = 0; nt < 4; nt++) {
                const int k0c = kb + nt * 8 + 2 * t;
                const int k1c = k0c + 1;
                float s0 = sc[mt][nt][0] * 0.125f;
                float s1 = sc[mt][nt][1] * 0.125f;
                float s2 = sc[mt][nt][2] * 0.125f;
                float s3 = sc[mt][nt][3] * 0.125f;
                s0 = (k0c <= qr0 && qr0 - k0c < WIN) ? s0 : -1e30f;
                s1 = (k1c <= qr0 && qr0 - k1c < WIN) ? s1 : -1e30f;
                s2 = (k0c <= qr1 && qr1 - k0c < WIN) ? s2 : -1e30f;
                s3 = (k1c <= qr1 && qr1 - k1c < WIN) ? s3 : -1e30f;
                sc[mt][nt][0] = s0; sc[mt][nt][1] = s1;
                sc[mt][nt][2] = s2; sc[mt][nt][3] = s3;
                mx0 = fmaxf(mx0, fmaxf(s0, s1));
                mx1 = fmaxf(mx1, fmaxf(s2, s3));
            }
            mx0 = fmaxf(mx0, __shfl_xor_sync(0xFFFFFFFFu, mx0, 1));
            mx0 = fmaxf(mx0, __shfl_xor_sync(0xFFFFFFFFu, mx0, 2));
            mx1 = fmaxf(mx1, __shfl_xor_sync(0xFFFFFFFFu, mx1, 1));
            mx1 = fmaxf(mx1, __shfl_xor_sync(0xFFFFFFFFu, mx1, 2));

            const float mn0 = fmaxf(m[mt][0], mx0);
            const float mn1 = fmaxf(m[mt][1], mx1);
            const float r0 = __expf(m[mt][0] - mn0);
            const float r1 = __expf(m[mt][1] - mn1);
            m[mt][0] = mn0; m[mt][1] = mn1;
            l[mt][0] *= r0; l[mt][1] *= r1;
#pragma unroll
            for (int nt = 0; nt < 8; nt++) {
                o[mt][nt][0] *= r0; o[mt][nt][1] *= r0;
                o[mt][nt][2] *= r1; o[mt][nt][3] *= r1;
            }
            unsigned* prow0 = &Ps[(wid * 32 + mt * 16 + g) * PPAD + 2 * t];
            unsigned* prow1 = prow0 + 8 * PPAD;
#pragma unroll
            for (int nt = 0; nt < 4; nt++) {
                float p0 = __expf(sc[mt][nt][0] - mn0);
                float p1 = __expf(sc[mt][nt][1] - mn0);
                float p2 = __expf(sc[mt][nt][2] - mn1);
                float p3 = __expf(sc[mt][nt][3] - mn1);
                l[mt][0] += p0 + p1;
                l[mt][1] += p2 + p3;
                prow0[nt * 8 + 0] = f2tf32(p0);
                prow0[nt * 8 + 1] = f2tf32(p1);
                prow1[nt * 8 + 0] = f2tf32(p2);
                prow1[nt * 8 + 1] = f2tf32(p3);
            }
        }
        __syncwarp();

        // ---- PV: P [32 rows][32 keys] x V [32 keys][64 dims] ----
#pragma unroll
        for (int kc = 0; kc < 4; kc++) {
            unsigned pa[2][4];
#pragma unroll
            for (int mt = 0; mt < 2; mt++) {
                const unsigned* pr = &Ps[(wid * 32 + mt * 16) * PPAD];
                pa[mt][0] = pr[(g) * PPAD + 8 * kc + t];
                pa[mt][1] = pr[(g + 8) * PPAD + 8 * kc + t];
                pa[mt][2] = pr[(g) * PPAD + 8 * kc + t + 4];
                pa[mt][3] = pr[(g + 8) * PPAD + 8 * kc + t + 4];
            }
#pragma unroll
            for (int nt = 0; nt < 8; nt++) {
                unsigned bv[2];
                bv[0] = Vs[(8 * kc + t) * KPAD + nt * 8 + g];
                bv[1] = Vs[(8 * kc + t + 4) * KPAD + nt * 8 + g];
#pragma unroll
                for (int mt = 0; mt < 2; mt++)
                    mma_tf32(o[mt][nt], pa[mt], bv);
            }
        }
    }

    // ---- finalize: add sink to denominator, normalize, write out ----
#pragma unroll
    for (int mt = 0; mt < 2; mt++) {
        float l0 = l[mt][0], l1 = l[mt][1];
        l0 += __shfl_xor_sync(0xFFFFFFFFu, l0, 1);
        l0 += __shfl_xor_sync(0xFFFFFFFFu, l0, 2);
        l1 += __shfl_xor_sync(0xFFFFFFFFu, l1, 1);
        l1 += __shfl_xor_sync(0xFFFFFFFFu, l1, 2);
        const float inv0 = 1.0f / (l0 + __expf(sink - m[mt][0]));
        const float inv1 = 1.0f / (l1 + __expf(sink - m[mt][1]));

        const int qr0 = q0 + mt * 16 + g;
        float* orow0 = out + ((size_t)(b * SEQ + qr0)) * (NH * HD) + (hk * GQA + wid) * HD;
        float* orow1 = orow0 + (size_t)8 * (NH * HD);
#pragma unroll
        for (int nt = 0; nt < 8; nt++) {
            float2 v0 = make_float2(o[mt][nt][0] * inv0, o[mt][nt][1] * inv0);
            float2 v1 = make_float2(o[mt][nt][2] * inv1, o[mt][nt][3] * inv1);
            *(float2*)(orow0 + nt * 8 + 2 * t) = v0;
            *(float2*)(orow1 + nt * 8 + 2 * t) = v1;
        }
    }
}

// ---------------------------------------------------------------------------
// kernel_launch
// Inputs: x, Wq, bq, Wk, bk, Wv, bv, Wo, bo, sinks
// ---------------------------------------------------------------------------
extern "C" void kernel_launch(void* const* d_in, const int* in_sizes, int n_in,
                              void* d_out, int out_size)
{
    const float* x    = (const float*)d_in[0];
    const float* Wq   = (const float*)d_in[1];
    const float* bq   = (const float*)d_in[2];
    const float* Wk   = (const float*)d_in[3];
    const float* bk   = (const float*)d_in[4];
    const float* Wv   = (const float*)d_in[5];
    const float* bv   = (const float*)d_in[6];
    const float* Wo   = (const float*)d_in[7];
    const float* bo   = (const float*)d_in[8];
    const float* sinks = (const float*)d_in[9];
    float* out = (float*)d_out;

    float* qkv = nullptr;
    float* attn = nullptr;
    cudaGetSymbolAddress((void**)&qkv, g_qkv);
    cudaGetSymbolAddress((void**)&attn, g_attn);

    static bool attr_set = false;
    if (!attr_set) {
        cudaFuncSetAttribute(attn_mma_kernel,
                             cudaFuncAttributeMaxDynamicSharedMemorySize, ATTN_SMEM);
        attr_set = true;
    }

    const int M = BATCH * SEQ;   // 2048

    // QKV projections into segmented buffer [M, 5120]
    {
        dim3 grid(NH * HD / 128, M / 128);     // 32 x 16
        tf32_gemm_nt<<<grid, 256>>>(x, Wq, bq, qkv + 0, M, NH * HD, DM, QKV_N);
    }
    {
        dim3 grid(NHK * HD / 128, M / 128);    // 4 x 16
        tf32_gemm_nt<<<grid, 256>>>(x, Wk, bk, qkv + K_OFF, M, NHK * HD, DM, QKV_N);
        tf32_gemm_nt<<<grid, 256>>>(x, Wv, bv, qkv + V_OFF, M, NHK * HD, DM, QKV_N);
    }

    // Attention (flash-style, tensor cores)
    {
        dim3 grid(SEQ / 32, NHK, BATCH);       // 32 x 8 x 2
        attn_mma_kernel<<<grid, 256, ATTN_SMEM>>>(qkv, sinks, attn);
    }

    // Output projection: C[M, DM] = attn[M, NH*HD] @ Wo[DM, NH*HD]^T + bo
    {
        dim3 grid(DM / 128, M / 128);          // 8 x 16
        tf32_gemm_nt<<<grid, 256>>>(attn, Wo, bo, out, M, DM, NH * HD, DM);
    }
}

// round 6
// speedup vs baseline: 5.4407x; 1.3140x over previous
#include <cuda_runtime.h>
#include <cuda_fp16.h>
#include <math.h>
#include <stdint.h>

// Problem constants
#define BATCH 2
#define SEQ   1024
#define DM    1024
#define NH    64
#define NHK   8
#define HD    64
#define WIN   128
#define GQA   8
#define QKV_N 5120
#define K_OFF 4096
#define V_OFF 4608

// Scratch (device globals)
__device__ __align__(16) float g_qkv[BATCH * SEQ * QKV_N];
__device__ __align__(16) float g_attn[BATCH * SEQ * NH * HD];

// ---------------------------------------------------------------------------
// helpers
// ---------------------------------------------------------------------------
__device__ __forceinline__ unsigned f2tf32(float x) {
    unsigned u;
    asm("cvt.rna.tf32.f32 %0, %1;" : "=r"(u) : "f"(x));
    return u;
}
__device__ __forceinline__ unsigned pack_h2(float a, float b) {
    __half2 h = __floats2half2_rn(a, b);
    return *(unsigned*)&h;
}

// fp16 mma m16n8k16, f32 accumulate
__device__ __forceinline__ void mma_f16(float* c, const unsigned* a, const unsigned* b) {
    asm volatile(
        "mma.sync.aligned.m16n8k16.row.col.f32.f16.f16.f32 "
        "{%0,%1,%2,%3}, {%4,%5,%6,%7}, {%8,%9}, {%0,%1,%2,%3};"
        : "+f"(c[0]), "+f"(c[1]), "+f"(c[2]), "+f"(c[3])
        : "r"(a[0]), "r"(a[1]), "r"(a[2]), "r"(a[3]), "r"(b[0]), "r"(b[1]));
}

// tf32 mma m16n8k8 (attention only)
__device__ __forceinline__ void mma_tf32(float* c, const unsigned* a, const unsigned* b) {
    asm volatile(
        "mma.sync.aligned.m16n8k8.row.col.f32.tf32.tf32.f32 "
        "{%0,%1,%2,%3}, {%4,%5,%6,%7}, {%8,%9}, {%0,%1,%2,%3};"
        : "+f"(c[0]), "+f"(c[1]), "+f"(c[2]), "+f"(c[3])
        : "r"(a[0]), "r"(a[1]), "r"(a[2]), "r"(a[3]), "r"(b[0]), "r"(b[1]));
}

// ---------------------------------------------------------------------------
// FP16 tensor-core GEMM core: C[128,128] tile = A[M,K] @ B[N,K]^T + bias
// 256 threads = 8 warps; warp = 32(M) x 64(N); BK=32 (2 k16 steps).
// Smem rows stored as half2 words, stride HPAD=20 -> conflict-free frags.
// ---------------------------------------------------------------------------
#define HPAD 20   // b32 words per smem row (16 data + 4 pad)

__device__ __forceinline__ void gemm_f16_core(
    const float* __restrict__ A,     // [M, K] activations (row by*128..)
    const float* __restrict__ Bg,    // [128, K] weight slice for this N tile
    const float* __restrict__ bias,  // 128 entries
    float* __restrict__ Cg,          // C base: add row*ldc + col
    int K, int ldc, int by, int colbase)
{
    __shared__ unsigned As[128 * HPAD];
    __shared__ unsigned Bs[128 * HPAD];

    const int tid  = threadIdx.x;
    const int wid  = tid >> 5;
    const int lane = tid & 31;
    const int wm   = wid & 3;
    const int wn   = wid >> 2;
    const int g    = lane >> 2;
    const int t    = lane & 3;

    const float* Ag = A + (size_t)(by * 128) * K;

    float acc[2][8][4];
#pragma unroll
    for (int mt = 0; mt < 2; mt++)
#pragma unroll
        for (int nt = 0; nt < 8; nt++)
#pragma unroll
            for (int i = 0; i < 4; i++) acc[mt][nt][i] = 0.0f;

    float4 stA[4], stB[4];
    const int niter = K >> 5;

#pragma unroll
    for (int p = 0; p < 4; p++) {
        int f = tid + p * 256;
        int row = f >> 3, c4 = f & 7;
        stA[p] = *(const float4*)(Ag + (size_t)row * K + c4 * 4);
        stB[p] = *(const float4*)(Bg + (size_t)row * K + c4 * 4);
    }

    for (int it = 0; it < niter; it++) {
        __syncthreads();
#pragma unroll
        for (int p = 0; p < 4; p++) {
            int f = tid + p * 256;
            int row = f >> 3, c4 = f & 7;
            uint2 ha = make_uint2(pack_h2(stA[p].x, stA[p].y), pack_h2(stA[p].z, stA[p].w));
            uint2 hb = make_uint2(pack_h2(stB[p].x, stB[p].y), pack_h2(stB[p].z, stB[p].w));
            *(uint2*)&As[row * HPAD + c4 * 2] = ha;
            *(uint2*)&Bs[row * HPAD + c4 * 2] = hb;
        }
        __syncthreads();

        if (it + 1 < niter) {
            int k0 = (it + 1) << 5;
#pragma unroll
            for (int p = 0; p < 4; p++) {
                int f = tid + p * 256;
                int row = f >> 3, c4 = f & 7;
                stA[p] = *(const float4*)(Ag + (size_t)row * K + k0 + c4 * 4);
                stB[p] = *(const float4*)(Bg + (size_t)row * K + k0 + c4 * 4);
            }
        }

        // 2 k-steps of k=16 (half2 cols kk*8 + t, + t + 4)
#pragma unroll
        for (int kk = 0; kk < 2; kk++) {
            const int k = kk * 8;
            unsigned a[2][4], b[8][2];
#pragma unroll
            for (int mt = 0; mt < 2; mt++) {
                const int rb = wm * 32 + mt * 16;
                a[mt][0] = As[(rb + g) * HPAD + k + t];
                a[mt][1] = As[(rb + 8 + g) * HPAD + k + t];
                a[mt][2] = As[(rb + g) * HPAD + k + t + 4];
                a[mt][3] = As[(rb + 8 + g) * HPAD + k + t + 4];
            }
#pragma unroll
            for (int nt = 0; nt < 8; nt++) {
                const int nb = wn * 64 + nt * 8;
                b[nt][0] = Bs[(nb + g) * HPAD + k + t];
                b[nt][1] = Bs[(nb + g) * HPAD + k + t + 4];
            }
#pragma unroll
            for (int mt = 0; mt < 2; mt++)
#pragma unroll
                for (int nt = 0; nt < 8; nt++)
                    mma_f16(acc[mt][nt], a[mt], b[nt]);
        }
    }

    // epilogue with bias
#pragma unroll
    for (int mt = 0; mt < 2; mt++) {
        const int row0 = by * 128 + wm * 32 + mt * 16 + g;
#pragma unroll
        for (int nt = 0; nt < 8; nt++) {
            const int col = wn * 64 + nt * 8 + 2 * t;
            const float b0 = bias[col], b1 = bias[col + 1];
            float2 o0 = make_float2(acc[mt][nt][0] + b0, acc[mt][nt][1] + b1);
            float2 o1 = make_float2(acc[mt][nt][2] + b0, acc[mt][nt][3] + b1);
            *(float2*)(Cg + (size_t)row0 * ldc + colbase + col) = o0;
            *(float2*)(Cg + (size_t)(row0 + 8) * ldc + colbase + col) = o1;
        }
    }
}

// Merged QKV projection: grid.x in [0,40): 0-31 Q, 32-35 K, 36-39 V
__global__ __launch_bounds__(256) void gemm_qkv(
    const float* __restrict__ A,
    const float* __restrict__ Wq, const float* __restrict__ bq,
    const float* __restrict__ Wk, const float* __restrict__ bk,
    const float* __restrict__ Wv, const float* __restrict__ bv,
    float* __restrict__ C)
{
    const int bx = blockIdx.x;
    const float* W; const float* bias; int wt, seg;
    if (bx < 32)      { W = Wq; bias = bq; wt = bx;      seg = 0; }
    else if (bx < 36) { W = Wk; bias = bk; wt = bx - 32; seg = K_OFF; }
    else              { W = Wv; bias = bv; wt = bx - 36; seg = V_OFF; }
    gemm_f16_core(A, W + (size_t)wt * 128 * DM, bias + wt * 128,
                  C, DM, QKV_N, blockIdx.y, seg + wt * 128);
}

// Output projection
__global__ __launch_bounds__(256) void gemm_out(
    const float* __restrict__ A, const float* __restrict__ B,
    const float* __restrict__ bias, float* __restrict__ C, int K, int ldc)
{
    gemm_f16_core(A, B + (size_t)blockIdx.x * 128 * K, bias + blockIdx.x * 128,
                  C, K, ldc, blockIdx.y, blockIdx.x * 128);
}

// ---------------------------------------------------------------------------
// Flash-style sliding-window GQA attention with sink logit (R4, unchanged)
// ---------------------------------------------------------------------------
#define KC   32
#define KPAD 68
#define PPAD 36
#define KS_OFF 0
#define VS_OFF (KC * KPAD)
#define PS_OFF (2 * KC * KPAD)
#define ATTN_SMEM ((2 * KC * KPAD + 256 * PPAD) * 4)

__global__ __launch_bounds__(256) void attn_mma_kernel(
    const float* __restrict__ qkv, const float* __restrict__ sinks,
    float* __restrict__ out)
{
    extern __shared__ unsigned asmem[];
    unsigned* Ks = asmem + KS_OFF;
    unsigned* Vs = asmem + VS_OFF;
    unsigned* Ps = asmem + PS_OFF;

    const int q0  = blockIdx.x * 32;
    const int hk  = blockIdx.y;
    const int b   = blockIdx.z;
    const int tid = threadIdx.x;
    const int wid = tid >> 5;
    const int lane = tid & 31;
    const int g = lane >> 2;
    const int t = lane & 3;

    const int kbase = (q0 >= 128) ? (q0 - 128) : 0;
    const int nch = (q0 + 32 - kbase) >> 5;

    unsigned qa[2][8][4];
    {
        const float* qrow = qkv + ((size_t)(b * SEQ + q0)) * QKV_N + hk * 512 + wid * 64;
#pragma unroll
        for (int mt = 0; mt < 2; mt++) {
            const float* r0 = qrow + (size_t)(mt * 16 + g) * QKV_N;
            const float* r1 = r0 + (size_t)8 * QKV_N;
#pragma unroll
            for (int k = 0; k < 8; k++) {
                qa[mt][k][0] = f2tf32(r0[8 * k + t]);
                qa[mt][k][1] = f2tf32(r1[8 * k + t]);
                qa[mt][k][2] = f2tf32(r0[8 * k + t + 4]);
                qa[mt][k][3] = f2tf32(r1[8 * k + t + 4]);
            }
        }
    }

    const float sink = sinks[hk * GQA + wid];
    float m[2][2], l[2][2];
#pragma unroll
    for (int mt = 0; mt < 2; mt++) { m[mt][0] = sink; m[mt][1] = sink; l[mt][0] = 0.f; l[mt][1] = 0.f; }

    float o[2][8][4];
#pragma unroll
    for (int mt = 0; mt < 2; mt++)
#pragma unroll
        for (int nt = 0; nt < 8; nt++)
#pragma unroll
            for (int i = 0; i < 4; i++) o[mt][nt][i] = 0.0f;

    const int ldrow = tid >> 4;
    const int ldc4  = tid & 15;

    for (int ch = 0; ch < nch; ch++) {
        const int kb = kbase + ch * KC;
        __syncthreads();
        {
            const size_t rowbase = ((size_t)(b * SEQ + kb + ldrow)) * QKV_N;
            const size_t rowbase2 = rowbase + (size_t)16 * QKV_N;
            float4 kv0 = *(const float4*)(qkv + rowbase + K_OFF + hk * 64 + ldc4 * 4);
            float4 kv1 = *(const float4*)(qkv + rowbase2 + K_OFF + hk * 64 + ldc4 * 4);
            float4 vv0 = *(const float4*)(qkv + rowbase + V_OFF + hk * 64 + ldc4 * 4);
            float4 vv1 = *(const float4*)(qkv + rowbase2 + V_OFF + hk * 64 + ldc4 * 4);
            unsigned* pk0 = &Ks[ldrow * KPAD + ldc4 * 4];
            unsigned* pk1 = &Ks[(ldrow + 16) * KPAD + ldc4 * 4];
            unsigned* pv0 = &Vs[ldrow * KPAD + ldc4 * 4];
            unsigned* pv1 = &Vs[(ldrow + 16) * KPAD + ldc4 * 4];
            pk0[0] = f2tf32(kv0.x); pk0[1] = f2tf32(kv0.y); pk0[2] = f2tf32(kv0.z); pk0[3] = f2tf32(kv0.w);
            pk1[0] = f2tf32(kv1.x); pk1[1] = f2tf32(kv1.y); pk1[2] = f2tf32(kv1.z); pk1[3] = f2tf32(kv1.w);
            pv0[0] = f2tf32(vv0.x); pv0[1] = f2tf32(vv0.y); pv0[2] = f2tf32(vv0.z); pv0[3] = f2tf32(vv0.w);
            pv1[0] = f2tf32(vv1.x); pv1[1] = f2tf32(vv1.y); pv1[2] = f2tf32(vv1.z); pv1[3] = f2tf32(vv1.w);
        }
        __syncthreads();

        float sc[2][4][4];
#pragma unroll
        for (int mt = 0; mt < 2; mt++)
#pragma unroll
            for (int nt = 0; nt < 4; nt++)
#pragma unroll
                for (int i = 0; i < 4; i++) sc[mt][nt][i] = 0.0f;

#pragma unroll
        for (int k = 0; k < 8; k++) {
            unsigned bfr[4][2];
#pragma unroll
            for (int nt = 0; nt < 4; nt++) {
                bfr[nt][0] = Ks[(nt * 8 + g) * KPAD + 8 * k + t];
                bfr[nt][1] = Ks[(nt * 8 + g) * KPAD + 8 * k + t + 4];
            }
#pragma unroll
            for (int mt = 0; mt < 2; mt++)
#pragma unroll
                for (int nt = 0; nt < 4; nt++)
                    mma_tf32(sc[mt][nt], qa[mt][k], bfr[nt]);
        }

#pragma unroll
        for (int mt = 0; mt < 2; mt++) {
            const int qr0 = q0 + mt * 16 + g;
            const int qr1 = qr0 + 8;
            float mx0 = -1e30f, mx1 = -1e30f;
#pragma unroll
            for (int nt = 0; nt < 4; nt++) {
                const int k0c = kb + nt * 8 + 2 * t;
                const int k1c = k0c + 1;
                float s0 = sc[mt][nt][0] * 0.125f;
                float s1 = sc[mt][nt][1] * 0.125f;
                float s2 = sc[mt][nt][2] * 0.125f;
                float s3 = sc[mt][nt][3] * 0.125f;
                s0 = (k0c <= qr0 && qr0 - k0c < WIN) ? s0 : -1e30f;
                s1 = (k1c <= qr0 && qr0 - k1c < WIN) ? s1 : -1e30f;
                s2 = (k0c <= qr1 && qr1 - k0c < WIN) ? s2 : -1e30f;
                s3 = (k1c <= qr1 && qr1 - k1c < WIN) ? s3 : -1e30f;
                sc[mt][nt][0] = s0; sc[mt][nt][1] = s1;
                sc[mt][nt][2] = s2; sc[mt][nt][3] = s3;
                mx0 = fmaxf(mx0, fmaxf(s0, s1));
                mx1 = fmaxf(mx1, fmaxf(s2, s3));
            }
            mx0 = fmaxf(mx0, __shfl_xor_sync(0xFFFFFFFFu, mx0, 1));
            mx0 = fmaxf(mx0, __shfl_xor_sync(0xFFFFFFFFu, mx0, 2));
            mx1 = fmaxf(mx1, __shfl_xor_sync(0xFFFFFFFFu, mx1, 1));
            mx1 = fmaxf(mx1, __shfl_xor_sync(0xFFFFFFFFu, mx1, 2));

            const float mn0 = fmaxf(m[mt][0], mx0);
            const float mn1 = fmaxf(m[mt][1], mx1);
            const float r0 = __expf(m[mt][0] - mn0);
            const float r1 = __expf(m[mt][1] - mn1);
            m[mt][0] = mn0; m[mt][1] = mn1;
            l[mt][0] *= r0; l[mt][1] *= r1;
#pragma unroll
            for (int nt = 0; nt < 8; nt++) {
                o[mt][nt][0] *= r0; o[mt][nt][1] *= r0;
                o[mt][nt][2] *= r1; o[mt][nt][3] *= r1;
            }
            unsigned* prow0 = &Ps[(wid * 32 + mt * 16 + g) * PPAD + 2 * t];
            unsigned* prow1 = prow0 + 8 * PPAD;
#pragma unroll
            for (int nt = 0; nt < 4; nt++) {
                float p0 = __expf(sc[mt][nt][0] - mn0);
                float p1 = __expf(sc[mt][nt][1] - mn0);
                float p2 = __expf(sc[mt][nt][2] - mn1);
                float p3 = __expf(sc[mt][nt][3] - mn1);
                l[mt][0] += p0 + p1;
                l[mt][1] += p2 + p3;
                prow0[nt * 8 + 0] = f2tf32(p0);
                prow0[nt * 8 + 1] = f2tf32(p1);
                prow1[nt * 8 + 0] = f2tf32(p2);
                prow1[nt * 8 + 1] = f2tf32(p3);
            }
        }
        __syncwarp();

#pragma unroll
        for (int kc = 0; kc < 4; kc++) {
            unsigned pa[2][4];
#pragma unroll
            for (int mt = 0; mt < 2; mt++) {
                const unsigned* pr = &Ps[(wid * 32 + mt * 16) * PPAD];
                pa[mt][0] = pr[(g) * PPAD + 8 * kc + t];
                pa[mt][1] = pr[(g + 8) * PPAD + 8 * kc + t];
                pa[mt][2] = pr[(g) * PPAD + 8 * kc + t + 4];
                pa[mt][3] = pr[(g + 8) * PPAD + 8 * kc + t + 4];
            }
#pragma unroll
            for (int nt = 0; nt < 8; nt++) {
                unsigned bv[2];
                bv[0] = Vs[(8 * kc + t) * KPAD + nt * 8 + g];
                bv[1] = Vs[(8 * kc + t + 4) * KPAD + nt * 8 + g];
#pragma unroll
                for (int mt = 0; mt < 2; mt++)
                    mma_tf32(o[mt][nt], pa[mt], bv);
            }
        }
    }

#pragma unroll
    for (int mt = 0; mt < 2; mt++) {
        float l0 = l[mt][0], l1 = l[mt][1];
        l0 += __shfl_xor_sync(0xFFFFFFFFu, l0, 1);
        l0 += __shfl_xor_sync(0xFFFFFFFFu, l0, 2);
        l1 += __shfl_xor_sync(0xFFFFFFFFu, l1, 1);
        l1 += __shfl_xor_sync(0xFFFFFFFFu, l1, 2);
        const float inv0 = 1.0f / (l0 + __expf(sink - m[mt][0]));
        const float inv1 = 1.0f / (l1 + __expf(sink - m[mt][1]));

        const int qr0 = q0 + mt * 16 + g;
        float* orow0 = out + ((size_t)(b * SEQ + qr0)) * (NH * HD) + (hk * GQA + wid) * HD;
        float* orow1 = orow0 + (size_t)8 * (NH * HD);
#pragma unroll
        for (int nt = 0; nt < 8; nt++) {
            float2 v0 = make_float2(o[mt][nt][0] * inv0, o[mt][nt][1] * inv0);
            float2 v1 = make_float2(o[mt][nt][2] * inv1, o[mt][nt][3] * inv1);
            *(float2*)(orow0 + nt * 8 + 2 * t) = v0;
            *(float2*)(orow1 + nt * 8 + 2 * t) = v1;
        }
    }
}

// ---------------------------------------------------------------------------
// kernel_launch
// ---------------------------------------------------------------------------
extern "C" void kernel_launch(void* const* d_in, const int* in_sizes, int n_in,
                              void* d_out, int out_size)
{
    const float* x    = (const float*)d_in[0];
    const float* Wq   = (const float*)d_in[1];
    const float* bq   = (const float*)d_in[2];
    const float* Wk   = (const float*)d_in[3];
    const float* bk   = (const float*)d_in[4];
    const float* Wv   = (const float*)d_in[5];
    const float* bv   = (const float*)d_in[6];
    const float* Wo   = (const float*)d_in[7];
    const float* bo   = (const float*)d_in[8];
    const float* sinks = (const float*)d_in[9];
    float* out = (float*)d_out;

    float* qkv = nullptr;
    float* attn = nullptr;
    cudaGetSymbolAddress((void**)&qkv, g_qkv);
    cudaGetSymbolAddress((void**)&attn, g_attn);

    static bool attr_set = false;
    if (!attr_set) {
        cudaFuncSetAttribute(attn_mma_kernel,
                             cudaFuncAttributeMaxDynamicSharedMemorySize, ATTN_SMEM);
        attr_set = true;
    }

    const int M = BATCH * SEQ;   // 2048

    // Merged QKV projection (fp16 tensor cores)
    {
        dim3 grid(40, M / 128);
        gemm_qkv<<<grid, 256>>>(x, Wq, bq, Wk, bk, Wv, bv, qkv);
    }

    // Attention (flash-style, tf32 tensor cores)
    {
        dim3 grid(SEQ / 32, NHK, BATCH);
        attn_mma_kernel<<<grid, 256, ATTN_SMEM>>>(qkv, sinks, attn);
    }

    // Output projection (fp16 tensor cores)
    {
        dim3 grid(DM / 128, M / 128);
        gemm_out<<<grid, 256>>>(attn, Wo, bo, out, NH * HD, DM);
    }
}

// round 7
// speedup vs baseline: 7.3166x; 1.3448x over previous
#include <cuda_runtime.h>
#include <cuda_fp16.h>
#include <math.h>
#include <stdint.h>

// Problem constants
#define BATCH 2
#define SEQ   1024
#define DM    1024
#define NH    64
#define NHK   8
#define HD    64
#define WIN   128
#define GQA   8
#define QKV_N 5120
#define K_OFF 4096
#define V_OFF 4608

// Scratch (device globals)
__device__ __align__(16) float  g_qkv[BATCH * SEQ * QKV_N];
__device__ __align__(16) __half g_xh[BATCH * SEQ * DM];
__device__ __align__(16) __half g_wqh[NH * HD * DM];
__device__ __align__(16) __half g_wkh[NHK * HD * DM];
__device__ __align__(16) __half g_wvh[NHK * HD * DM];
__device__ __align__(16) __half g_woh[DM * NH * HD];
__device__ __align__(16) __half g_attnh[BATCH * SEQ * NH * HD];

// ---------------------------------------------------------------------------
// helpers
// ---------------------------------------------------------------------------
__device__ __forceinline__ unsigned f2tf32(float x) {
    unsigned u;
    asm("cvt.rna.tf32.f32 %0, %1;" : "=r"(u) : "f"(x));
    return u;
}
__device__ __forceinline__ unsigned pack_h2(float a, float b) {
    __half2 h = __floats2half2_rn(a, b);
    return *(unsigned*)&h;
}
__device__ __forceinline__ uint32_t smem_u32(const void* p) {
    uint32_t a;
    asm("{ .reg .u64 t; cvta.to.shared.u64 t, %1; cvt.u32.u64 %0, t; }" : "=r"(a) : "l"(p));
    return a;
}
#define CP16(dst, src) \
    asm volatile("cp.async.cg.shared.global [%0], [%1], 16;" \
        :: "r"(dst), "l"(__cvta_generic_to_global(src)))
#define CP_COMMIT() asm volatile("cp.async.commit_group;")
#define CP_WAIT(n)  asm volatile("cp.async.wait_group %0;" :: "n"(n))

__device__ __forceinline__ void mma_f16(float* c, const unsigned* a, const unsigned* b) {
    asm volatile(
        "mma.sync.aligned.m16n8k16.row.col.f32.f16.f16.f32 "
        "{%0,%1,%2,%3}, {%4,%5,%6,%7}, {%8,%9}, {%0,%1,%2,%3};"
        : "+f"(c[0]), "+f"(c[1]), "+f"(c[2]), "+f"(c[3])
        : "r"(a[0]), "r"(a[1]), "r"(a[2]), "r"(a[3]), "r"(b[0]), "r"(b[1]));
}
__device__ __forceinline__ void mma_tf32(float* c, const unsigned* a, const unsigned* b) {
    asm volatile(
        "mma.sync.aligned.m16n8k8.row.col.f32.tf32.tf32.f32 "
        "{%0,%1,%2,%3}, {%4,%5,%6,%7}, {%8,%9}, {%0,%1,%2,%3};"
        : "+f"(c[0]), "+f"(c[1]), "+f"(c[2]), "+f"(c[3])
        : "r"(a[0]), "r"(a[1]), "r"(a[2]), "r"(a[3]), "r"(b[0]), "r"(b[1]));
}

// ---------------------------------------------------------------------------
// fp32 -> fp16 conversion of x + all weights (one kernel)
// segments in float4 units: x 524288 | Wq 1048576 | Wk 131072 | Wv 131072 | Wo 1048576
// ---------------------------------------------------------------------------
#define CVT_TOTAL4 2883584
__global__ __launch_bounds__(256) void cvt_kernel(
    const float* __restrict__ x,  const float* __restrict__ wq,
    const float* __restrict__ wk, const float* __restrict__ wv,
    const float* __restrict__ wo)
{
    size_t i = (size_t)blockIdx.x * 256 + threadIdx.x;
    const float* src; __half* dst; size_t off;
    if (i < 524288)       { src = x;  dst = g_xh;  off = i; }
    else if (i < 1572864) { src = wq; dst = g_wqh; off = i - 524288; }
    else if (i < 1703936) { src = wk; dst = g_wkh; off = i - 1572864; }
    else if (i < 1835008) { src = wv; dst = g_wvh; off = i - 1703936; }
    else                  { src = wo; dst = g_woh; off = i - 1835008; }
    float4 v = ((const float4*)src)[off];
    ((uint2*)dst)[off] = make_uint2(pack_h2(v.x, v.y), pack_h2(v.z, v.w));
}

// ---------------------------------------------------------------------------
// FP16 GEMM core with cp.async 3-stage pipeline.
// C[128,128] tile = A[M,K](half) @ B[128,K](half)^T + bias(f32), C f32.
// Smem: rows of 32 halves (64B = 4 x 16B chunks), chunk swizzle c ^ ((r>>1)&3).
// 256 threads = 8 warps, warp = 32(M) x 64(N).
// ---------------------------------------------------------------------------
#define ST_WORDS 2048              // words per stage per matrix (128*16)
#define B_BASE   6144              // word offset of B stages (3*2048)

__device__ __forceinline__ void gemm_h_core(
    const __half* __restrict__ A, const __half* __restrict__ Bw,
    const float* __restrict__ bias, float* __restrict__ Cg,
    int K, int ldc, int by, int colbase)
{
    __shared__ uint32_t S[12288];   // 48KB: A[3][2048] + B[3][2048]

    const int tid  = threadIdx.x;
    const int wid  = tid >> 5;
    const int lane = tid & 31;
    const int wm   = wid & 3;
    const int wn   = wid >> 2;
    const int g    = lane >> 2;
    const int t    = lane & 3;

    const __half* Ag = A + (size_t)(by * 128) * K;

    // cp.async geometry: thread -> row r, chunks cb, cb+1
    const int r  = tid >> 1;
    const int cb = (tid & 1) * 2;
    const int sw = (r >> 1) & 3;
    const uint32_t sb = smem_u32(S);
    const uint32_t ad0 = sb + r * 64 + (((cb + 0) ^ sw) << 4);
    const uint32_t ad1 = sb + r * 64 + (((cb + 1) ^ sw) << 4);
    const __half* arow = Ag + (size_t)r * K + cb * 8;
    const __half* brow = Bw + (size_t)r * K + cb * 8;

    float acc[2][8][4];
#pragma unroll
    for (int mt = 0; mt < 2; mt++)
#pragma unroll
        for (int nt = 0; nt < 8; nt++)
#pragma unroll
            for (int i = 0; i < 4; i++) acc[mt][nt][i] = 0.0f;

    const int niter = K >> 5;

#pragma unroll
    for (int s = 0; s < 2; s++) {
        const uint32_t bo = s * 8192;
        CP16(ad0 + bo, arow + s * 32);
        CP16(ad1 + bo, arow + s * 32 + 8);
        CP16(ad0 + bo + 24576, brow + s * 32);
        CP16(ad1 + bo + 24576, brow + s * 32 + 8);
        CP_COMMIT();
    }

    for (int it = 0; it < niter; it++) {
        const int buf = it % 3;
        if (it + 1 < niter) { CP_WAIT(1); } else { CP_WAIT(0); }
        __syncthreads();

        const uint32_t* SA = S + buf * ST_WORDS;
        const uint32_t* SB = S + B_BASE + buf * ST_WORDS;

#pragma unroll
        for (int kk = 0; kk < 2; kk++) {
            const int c0 = kk * 2, c1 = kk * 2 + 1;
            unsigned a[2][4], b[8][2];
#pragma unroll
            for (int mt = 0; mt < 2; mt++) {
                const int row0 = wm * 32 + mt * 16 + g;
                const int row1 = row0 + 8;
                const int s0 = (row0 >> 1) & 3, s1 = (row1 >> 1) & 3;
                a[mt][0] = SA[row0 * 16 + ((c0 ^ s0) << 2) + t];
                a[mt][1] = SA[row1 * 16 + ((c0 ^ s1) << 2) + t];
                a[mt][2] = SA[row0 * 16 + ((c1 ^ s0) << 2) + t];
                a[mt][3] = SA[row1 * 16 + ((c1 ^ s1) << 2) + t];
            }
#pragma unroll
            for (int nt = 0; nt < 8; nt++) {
                const int rn = wn * 64 + nt * 8 + g;
                const int sn = (rn >> 1) & 3;
                b[nt][0] = SB[rn * 16 + ((c0 ^ sn) << 2) + t];
                b[nt][1] = SB[rn * 16 + ((c1 ^ sn) << 2) + t];
            }
#pragma unroll
            for (int mt = 0; mt < 2; mt++)
#pragma unroll
                for (int nt = 0; nt < 8; nt++)
                    mma_f16(acc[mt][nt], a[mt], b[nt]);
        }

        if (it + 2 < niter) {
            const int s = it + 2;
            const uint32_t bo = (s % 3) * 8192;
            CP16(ad0 + bo, arow + s * 32);
            CP16(ad1 + bo, arow + s * 32 + 8);
            CP16(ad0 + bo + 24576, brow + s * 32);
            CP16(ad1 + bo + 24576, brow + s * 32 + 8);
            CP_COMMIT();
        }
        __syncthreads();
    }

    // epilogue with bias
#pragma unroll
    for (int mt = 0; mt < 2; mt++) {
        const int row0 = by * 128 + wm * 32 + mt * 16 + g;
#pragma unroll
        for (int nt = 0; nt < 8; nt++) {
            const int col = wn * 64 + nt * 8 + 2 * t;
            const float b0 = bias[col], b1 = bias[col + 1];
            float2 o0 = make_float2(acc[mt][nt][0] + b0, acc[mt][nt][1] + b1);
            float2 o1 = make_float2(acc[mt][nt][2] + b0, acc[mt][nt][3] + b1);
            *(float2*)(Cg + (size_t)row0 * ldc + colbase + col) = o0;
            *(float2*)(Cg + (size_t)(row0 + 8) * ldc + colbase + col) = o1;
        }
    }
}

// Merged QKV projection: grid.x in [0,40): 0-31 Q, 32-35 K, 36-39 V
__global__ __launch_bounds__(256, 2) void gemm_qkv(
    const float* __restrict__ bq, const float* __restrict__ bk,
    const float* __restrict__ bv, float* __restrict__ C)
{
    const int bx = blockIdx.x;
    const __half* W; const float* bias; int wt, seg;
    if (bx < 32)      { W = g_wqh; bias = bq; wt = bx;      seg = 0; }
    else if (bx < 36) { W = g_wkh; bias = bk; wt = bx - 32; seg = K_OFF; }
    else              { W = g_wvh; bias = bv; wt = bx - 36; seg = V_OFF; }
    gemm_h_core(g_xh, W + (size_t)wt * 128 * DM, bias + wt * 128,
                C, DM, QKV_N, blockIdx.y, seg + wt * 128);
}

// Output projection: A = g_attnh [2048, 4096], B = g_woh
__global__ __launch_bounds__(256, 2) void gemm_out(
    const float* __restrict__ bias, float* __restrict__ C)
{
    gemm_h_core(g_attnh, g_woh + (size_t)blockIdx.x * 128 * (NH * HD),
                bias + blockIdx.x * 128, C, NH * HD, DM, blockIdx.y, blockIdx.x * 128);
}

// ---------------------------------------------------------------------------
// Flash-style sliding-window GQA attention with sink logit.
// Unchanged math from R4; output written as fp16 into g_attnh.
// ---------------------------------------------------------------------------
#define KC   32
#define KPAD 68
#define PPAD 36
#define KS_OFF 0
#define VS_OFF (KC * KPAD)
#define PS_OFF (2 * KC * KPAD)
#define ATTN_SMEM ((2 * KC * KPAD + 256 * PPAD) * 4)

__global__ __launch_bounds__(256) void attn_mma_kernel(
    const float* __restrict__ qkv, const float* __restrict__ sinks,
    __half* __restrict__ out)
{
    extern __shared__ unsigned asmem[];
    unsigned* Ks = asmem + KS_OFF;
    unsigned* Vs = asmem + VS_OFF;
    unsigned* Ps = asmem + PS_OFF;

    const int q0  = blockIdx.x * 32;
    const int hk  = blockIdx.y;
    const int b   = blockIdx.z;
    const int tid = threadIdx.x;
    const int wid = tid >> 5;
    const int lane = tid & 31;
    const int g = lane >> 2;
    const int t = lane & 3;

    const int kbase = (q0 >= 128) ? (q0 - 128) : 0;
    const int nch = (q0 + 32 - kbase) >> 5;

    unsigned qa[2][8][4];
    {
        const float* qrow = qkv + ((size_t)(b * SEQ + q0)) * QKV_N + hk * 512 + wid * 64;
#pragma unroll
        for (int mt = 0; mt < 2; mt++) {
            const float* r0 = qrow + (size_t)(mt * 16 + g) * QKV_N;
            const float* r1 = r0 + (size_t)8 * QKV_N;
#pragma unroll
            for (int k = 0; k < 8; k++) {
                qa[mt][k][0] = f2tf32(r0[8 * k + t]);
                qa[mt][k][1] = f2tf32(r1[8 * k + t]);
                qa[mt][k][2] = f2tf32(r0[8 * k + t + 4]);
                qa[mt][k][3] = f2tf32(r1[8 * k + t + 4]);
            }
        }
    }

    const float sink = sinks[hk * GQA + wid];
    float m[2][2], l[2][2];
#pragma unroll
    for (int mt = 0; mt < 2; mt++) { m[mt][0] = sink; m[mt][1] = sink; l[mt][0] = 0.f; l[mt][1] = 0.f; }

    float o[2][8][4];
#pragma unroll
    for (int mt = 0; mt < 2; mt++)
#pragma unroll
        for (int nt = 0; nt < 8; nt++)
#pragma unroll
            for (int i = 0; i < 4; i++) o[mt][nt][i] = 0.0f;

    const int ldrow = tid >> 4;
    const int ldc4  = tid & 15;

    for (int ch = 0; ch < nch; ch++) {
        const int kb = kbase + ch * KC;
        __syncthreads();
        {
            const size_t rowbase = ((size_t)(b * SEQ + kb + ldrow)) * QKV_N;
            const size_t rowbase2 = rowbase + (size_t)16 * QKV_N;
            float4 kv0 = *(const float4*)(qkv + rowbase + K_OFF + hk * 64 + ldc4 * 4);
            float4 kv1 = *(const float4*)(qkv + rowbase2 + K_OFF + hk * 64 + ldc4 * 4);
            float4 vv0 = *(const float4*)(qkv + rowbase + V_OFF + hk * 64 + ldc4 * 4);
            float4 vv1 = *(const float4*)(qkv + rowbase2 + V_OFF + hk * 64 + ldc4 * 4);
            unsigned* pk0 = &Ks[ldrow * KPAD + ldc4 * 4];
            unsigned* pk1 = &Ks[(ldrow + 16) * KPAD + ldc4 * 4];
            unsigned* pv0 = &Vs[ldrow * KPAD + ldc4 * 4];
            unsigned* pv1 = &Vs[(ldrow + 16) * KPAD + ldc4 * 4];
            pk0[0] = f2tf32(kv0.x); pk0[1] = f2tf32(kv0.y); pk0[2] = f2tf32(kv0.z); pk0[3] = f2tf32(kv0.w);
            pk1[0] = f2tf32(kv1.x); pk1[1] = f2tf32(kv1.y); pk1[2] = f2tf32(kv1.z); pk1[3] = f2tf32(kv1.w);
            pv0[0] = f2tf32(vv0.x); pv0[1] = f2tf32(vv0.y); pv0[2] = f2tf32(vv0.z); pv0[3] = f2tf32(vv0.w);
            pv1[0] = f2tf32(vv1.x); pv1[1] = f2tf32(vv1.y); pv1[2] = f2tf32(vv1.z); pv1[3] = f2tf32(vv1.w);
        }
        __syncthreads();

        float sc[2][4][4];
#pragma unroll
        for (int mt = 0; mt < 2; mt++)
#pragma unroll
            for (int nt = 0; nt < 4; nt++)
#pragma unroll
                for (int i = 0; i < 4; i++) sc[mt][nt][i] = 0.0f;

#pragma unroll
        for (int k = 0; k < 8; k++) {
            unsigned bfr[4][2];
#pragma unroll
            for (int nt = 0; nt < 4; nt++) {
                bfr[nt][0] = Ks[(nt * 8 + g) * KPAD + 8 * k + t];
                bfr[nt][1] = Ks[(nt * 8 + g) * KPAD + 8 * k + t + 4];
            }
#pragma unroll
            for (int mt = 0; mt < 2; mt++)
#pragma unroll
                for (int nt = 0; nt < 4; nt++)
                    mma_tf32(sc[mt][nt], qa[mt][k], bfr[nt]);
        }

#pragma unroll
        for (int mt = 0; mt < 2; mt++) {
            const int qr0 = q0 + mt * 16 + g;
            const int qr1 = qr0 + 8;
            float mx0 = -1e30f, mx1 = -1e30f;
#pragma unroll
            for (int nt = 0; nt < 4; nt++) {
                const int k0c = kb + nt * 8 + 2 * t;
                const int k1c = k0c + 1;
                float s0 = sc[mt][nt][0] * 0.125f;
                float s1 = sc[mt][nt][1] * 0.125f;
                float s2 = sc[mt][nt][2] * 0.125f;
                float s3 = sc[mt][nt][3] * 0.125f;
                s0 = (k0c <= qr0 && qr0 - k0c < WIN) ? s0 : -1e30f;
                s1 = (k1c <= qr0 && qr0 - k1c < WIN) ? s1 : -1e30f;
                s2 = (k0c <= qr1 && qr1 - k0c < WIN) ? s2 : -1e30f;
                s3 = (k1c <= qr1 && qr1 - k1c < WIN) ? s3 : -1e30f;
                sc[mt][nt][0] = s0; sc[mt][nt][1] = s1;
                sc[mt][nt][2] = s2; sc[mt][nt][3] = s3;
                mx0 = fmaxf(mx0, fmaxf(s0, s1));
                mx1 = fmaxf(mx1, fmaxf(s2, s3));
            }
            mx0 = fmaxf(mx0, __shfl_xor_sync(0xFFFFFFFFu, mx0, 1));
            mx0 = fmaxf(mx0, __shfl_xor_sync(0xFFFFFFFFu, mx0, 2));
            mx1 = fmaxf(mx1, __shfl_xor_sync(0xFFFFFFFFu, mx1, 1));
            mx1 = fmaxf(mx1, __shfl_xor_sync(0xFFFFFFFFu, mx1, 2));

            const float mn0 = fmaxf(m[mt][0], mx0);
            const float mn1 = fmaxf(m[mt][1], mx1);
            const float r0 = __expf(m[mt][0] - mn0);
            const float r1 = __expf(m[mt][1] - mn1);
            m[mt][0] = mn0; m[mt][1] = mn1;
            l[mt][0] *= r0; l[mt][1] *= r1;
#pragma unroll
            for (int nt = 0; nt < 8; nt++) {
                o[mt][nt][0] *= r0; o[mt][nt][1] *= r0;
                o[mt][nt][2] *= r1; o[mt][nt][3] *= r1;
            }
            unsigned* prow0 = &Ps[(wid * 32 + mt * 16 + g) * PPAD + 2 * t];
            unsigned* prow1 = prow0 + 8 * PPAD;
#pragma unroll
            for (int nt = 0; nt < 4; nt++) {
                float p0 = __expf(sc[mt][nt][0] - mn0);
                float p1 = __expf(sc[mt][nt][1] - mn0);
                float p2 = __expf(sc[mt][nt][2] - mn1);
                float p3 = __expf(sc[mt][nt][3] - mn1);
                l[mt][0] += p0 + p1;
                l[mt][1] += p2 + p3;
                prow0[nt * 8 + 0] = f2tf32(p0);
                prow0[nt * 8 + 1] = f2tf32(p1);
                prow1[nt * 8 + 0] = f2tf32(p2);
                prow1[nt * 8 + 1] = f2tf32(p3);
            }
        }
        __syncwarp();

#pragma unroll
        for (int kc = 0; kc < 4; kc++) {
            unsigned pa[2][4];
#pragma unroll
            for (int mt = 0; mt < 2; mt++) {
                const unsigned* pr = &Ps[(wid * 32 + mt * 16) * PPAD];
                pa[mt][0] = pr[(g) * PPAD + 8 * kc + t];
                pa[mt][1] = pr[(g + 8) * PPAD + 8 * kc + t];
                pa[mt][2] = pr[(g) * PPAD + 8 * kc + t + 4];
                pa[mt][3] = pr[(g + 8) * PPAD + 8 * kc + t + 4];
            }
#pragma unroll
            for (int nt = 0; nt < 8; nt++) {
                unsigned bv[2];
                bv[0] = Vs[(8 * kc + t) * KPAD + nt * 8 + g];
                bv[1] = Vs[(8 * kc + t + 4) * KPAD + nt * 8 + g];
#pragma unroll
                for (int mt = 0; mt < 2; mt++)
                    mma_tf32(o[mt][nt], pa[mt], bv);
            }
        }
    }

#pragma unroll
    for (int mt = 0; mt < 2; mt++) {
        float l0 = l[mt][0], l1 = l[mt][1];
        l0 += __shfl_xor_sync(0xFFFFFFFFu, l0, 1);
        l0 += __shfl_xor_sync(0xFFFFFFFFu, l0, 2);
        l1 += __shfl_xor_sync(0xFFFFFFFFu, l1, 1);
        l1 += __shfl_xor_sync(0xFFFFFFFFu, l1, 2);
        const float inv0 = 1.0f / (l0 + __expf(sink - m[mt][0]));
        const float inv1 = 1.0f / (l1 + __expf(sink - m[mt][1]));

        const int qr0 = q0 + mt * 16 + g;
        __half* orow0 = out + ((size_t)(b * SEQ + qr0)) * (NH * HD) + (hk * GQA + wid) * HD;
        __half* orow1 = orow0 + (size_t)8 * (NH * HD);
#pragma unroll
        for (int nt = 0; nt < 8; nt++) {
            *(unsigned*)(orow0 + nt * 8 + 2 * t) = pack_h2(o[mt][nt][0] * inv0, o[mt][nt][1] * inv0);
            *(unsigned*)(orow1 + nt * 8 + 2 * t) = pack_h2(o[mt][nt][2] * inv1, o[mt][nt][3] * inv1);
        }
    }
}

// ---------------------------------------------------------------------------
// kernel_launch
// ---------------------------------------------------------------------------
extern "C" void kernel_launch(void* const* d_in, const int* in_sizes, int n_in,
                              void* d_out, int out_size)
{
    const float* x    = (const float*)d_in[0];
    const float* Wq   = (const float*)d_in[1];
    const float* bq   = (const float*)d_in[2];
    const float* Wk   = (const float*)d_in[3];
    const float* bk   = (const float*)d_in[4];
    const float* Wv   = (const float*)d_in[5];
    const float* bv   = (const float*)d_in[6];
    const float* Wo   = (const float*)d_in[7];
    const float* bo   = (const float*)d_in[8];
    const float* sinks = (const float*)d_in[9];
    float* out = (float*)d_out;

    float* qkv = nullptr;
    __half* attnh = nullptr;
    cudaGetSymbolAddress((void**)&qkv, g_qkv);
    cudaGetSymbolAddress((void**)&attnh, g_attnh);

    static bool attr_set = false;
    if (!attr_set) {
        cudaFuncSetAttribute(attn_mma_kernel,
                             cudaFuncAttributeMaxDynamicSharedMemorySize, ATTN_SMEM);
        attr_set = true;
    }

    const int M = BATCH * SEQ;   // 2048

    // fp32 -> fp16 conversion of x and all weights
    cvt_kernel<<<CVT_TOTAL4 / 256, 256>>>(x, Wq, Wk, Wv, Wo);

    // Merged QKV projection (fp16 tensor cores, cp.async pipeline)
    {
        dim3 grid(40, M / 128);
        gemm_qkv<<<grid, 256>>>(bq, bk, bv, qkv);
    }

    // Attention (flash-style, tf32 tensor cores) -> fp16 output
    {
        dim3 grid(SEQ / 32, NHK, BATCH);
        attn_mma_kernel<<<grid, 256, ATTN_SMEM>>>(qkv, sinks, attnh);
    }

    // Output projection (fp16 tensor cores)
    {
        dim3 grid(DM / 128, M / 128);
        gemm_out<<<grid, 256>>>(bo, out);
    }
}